// round 16
// baseline (speedup 1.0000x reference)
#include <cuda_runtime.h>
#include <math.h>
#include <float.h>

#define BB  32
#define TT  20
#define CC  512
#define PP  196
#define HH  1024
#define NCC 101
#define NTHR 512
#define NSEG1 12        // part1: segs 0-3 = Wih1@Y, segs 4-11 = Whh1@h1
#define NSEG2 16        // part2: segs 0-7 = Wih2@h1new, segs 8-15 = Whh2@h2

// pools
#define PL_ATTN 0
#define PL_SG   1
#define PL_G1I  2
#define PL_G1R  3
#define PL_G2R  4
#define PL_G2I  5
#define PL_EPI1 6
#define PL_EPI2 7
#define SZ_ATTN 256
#define SZ_SG   256
#define SZ_G1I  64
#define SZ_G1R  128
#define SZ_G2R  128
#define SZ_G2I  128
#define SZ_EPI1 65      // unit 64 = beta
#define SZ_EPI2 64

typedef unsigned long long ull;

// ---------------- scratch ----------------
__device__ float g_sA2[TT * BB * PP];
__device__ float g_alogits[BB * 208];
__device__ float g_alphas[TT * BB * PP];
__device__ float g_h1T[2][HH * BB];
__device__ float g_h2T[2][HH * BB];
__device__ float g_h2BH[BB * HH];
__device__ float g_c1T[HH * BB];
__device__ float g_c2T[HH * BB];
__device__ float g_YT[CC * BB];
__device__ float g_betas[TT * BB];
__device__ float g_outs[TT * BB * NCC];
__device__ float g_part1[NSEG1][HH * 4 * BB];
__device__ float g_part2[NSEG2][HH * 4 * BB];
__device__ int g_tick[TT][8];

__device__ unsigned g_bar_gen;
__device__ unsigned g_bar_cnt;

__device__ __forceinline__ float sigm(float x) { return 1.f / (1.f + expf(-x)); }
__device__ __forceinline__ void fma2(ull& d, ull a, ull b) {
    asm("fma.rn.f32x2 %0, %1, %2, %0;" : "+l"(d) : "l"(a), "l"(b));
}
__device__ __forceinline__ ull dup2(float a) {
    ull r; asm("mov.b64 %0, {%1, %1};" : "=l"(r) : "f"(a)); return r;
}
__device__ __forceinline__ void unpack2(ull v, float& lo, float& hi) {
    asm("mov.b64 {%0, %1}, %2;" : "=f"(lo), "=f"(hi) : "l"(v));
}

// ---------------- block-wide GEMM unit: 64 jj x 4 gates x 128 k x 32 b ----------------
// u = sl*16 + jjblock(0..15); all 512 threads; 2 syncthreads per 32k tile.
__device__ __forceinline__ void gemm_bu(
    int pool, int u, int t, int tid,
    const float* __restrict__ Wih1, const float* __restrict__ Whh1,
    const float* __restrict__ Wih2, const float* __restrict__ Whh2,
    float* __restrict__ s_as, float* __restrict__ s_ws)
{
    const int lane = tid & 31, w = tid >> 5;
    const int r = tid & 255, kh = tid >> 8;
    const int sl = u >> 4, jjb = (u & 15) * 64;

    const float* act; const float* W; float* part; int Kw, seg;
    if (pool == PL_G1I)      { act = g_YT;               W = Wih1; Kw = CC; seg = sl;     part = &g_part1[0][0]; }
    else if (pool == PL_G1R) { act = g_h1T[t & 1];       W = Whh1; Kw = HH; seg = 4 + sl; part = &g_part1[0][0]; }
    else if (pool == PL_G2R) { act = g_h2T[t & 1];       W = Whh2; Kw = HH; seg = 8 + sl; part = &g_part2[0][0]; }
    else                     { act = g_h1T[(t + 1) & 1]; W = Wih2; Kw = HH; seg = sl;     part = &g_part2[0][0]; }
    const int k0 = sl * 128;

    const float* wsrc = W + ((size_t)((r & 3) * HH + jjb + (r >> 2))) * Kw + k0 + kh * 16;
    const float* abase = act + (size_t)k0 * BB;

    ull acc[8];
#pragma unroll
    for (int i = 0; i < 8; i++) acc[i] = 0ull;
    const int rowbase = w * 16;

    float4 w4[4]; float4 a4 = make_float4(0.f, 0.f, 0.f, 0.f);
#pragma unroll
    for (int i = 0; i < 4; i++) w4[i] = ((const float4*)wsrc)[i];
    if (tid < 256) a4 = ((const float4*)abase)[tid];

#pragma unroll
    for (int tile = 0; tile < 4; tile++) {
        __syncthreads();
        if (tid < 256) ((float4*)s_as)[tid] = a4;
#pragma unroll
        for (int i = 0; i < 4; i++) {
            int kk = kh * 16 + 4 * i;
            s_ws[(kk + 0) * 256 + r] = w4[i].x;
            s_ws[(kk + 1) * 256 + r] = w4[i].y;
            s_ws[(kk + 2) * 256 + r] = w4[i].z;
            s_ws[(kk + 3) * 256 + r] = w4[i].w;
        }
        __syncthreads();
        if (tile < 3) {
            const float4* wn = (const float4*)(wsrc + (tile + 1) * 32);
#pragma unroll
            for (int i = 0; i < 4; i++) w4[i] = wn[i];
            if (tid < 256) a4 = ((const float4*)(abase + (tile + 1) * 32 * BB))[tid];
        }
#pragma unroll
        for (int k = 0; k < 32; k++) {
            ull a2 = dup2(s_as[k * 32 + lane]);
#pragma unroll
            for (int j = 0; j < 4; j++) {
                ulonglong2 wv = *(const ulonglong2*)&s_ws[k * 256 + rowbase + 4 * j];
                fma2(acc[2 * j], a2, wv.x);
                fma2(acc[2 * j + 1], a2, wv.y);
            }
        }
    }

    float* dstb = part + (size_t)seg * (HH * 4 * BB) + jjb * 128 + lane;
#pragma unroll
    for (int j = 0; j < 4; j++) {
        float f0, f1, f2, f3;
        unpack2(acc[2 * j], f0, f1);
        unpack2(acc[2 * j + 1], f2, f3);
        int rr = rowbase + 4 * j;
        dstb[(rr + 0) * 32] = f0; dstb[(rr + 1) * 32] = f1;
        dstb[(rr + 2) * 32] = f2; dstb[(rr + 3) * 32] = f3;
    }
}

// ---------------- persistent mega-kernel ----------------
__global__ void __launch_bounds__(NTHR, 1) mega_kernel(
    const float* __restrict__ videos,
    const float* __restrict__ h1, const float* __restrict__ c1,
    const float* __restrict__ h2, const float* __restrict__ c2,
    const float* __restrict__ spatialBias, const float* __restrict__ temporalBias,
    const float* __restrict__ W_h2p, const float* __restrict__ b_h2p,
    const float* __restrict__ W_sC21, const float* __restrict__ b_sC21,
    const float* __restrict__ W_h21, const float* __restrict__ b_h21,
    const float* __restrict__ W_tC21, const float* __restrict__ b_tC21,
    const float* __restrict__ Wih1, const float* __restrict__ Whh1,
    const float* __restrict__ bih1, const float* __restrict__ bhh1,
    const float* __restrict__ Wih2, const float* __restrict__ Whh2,
    const float* __restrict__ bih2, const float* __restrict__ bhh2,
    const float* __restrict__ W_fc, const float* __restrict__ b_fc,
    float* __restrict__ out, int write_alphas, int write_betas)
{
    __shared__ __align__(16) float s_arena[9216];   // 36KB: gemm s_as(1024)+s_ws(8192)
    float* s_as  = s_arena;
    float* s_ws  = s_arena + 1024;
    float* s_red = s_arena;             // overlays (phase-exclusive)
    float* s_al  = s_arena + 512;
    float* s_h2  = s_arena + 1024;
    float* s_wsc = s_arena + 2048;
    float* s_bw  = s_arena + 2560;

    __shared__ int s_u;
    __shared__ unsigned s_gen;
    __shared__ int s_st, s_pool, s_idx, s_t;

    const int tid = threadIdx.x, lane = tid & 31, w = tid >> 5;
    const int NBK = gridDim.x;

    const int LOGITS = BB * NCC;
    const int ALPHAS = TT * BB * PP;

    // ======== barrier with slack stealing (block-wide) ========
    auto barrier_slack = [&](int pa, int sza, int ta, int pb, int szb, int tb) {
        __syncthreads();
        if (tid == 0) {
            unsigned gen = *(volatile unsigned*)&g_bar_gen;
            s_gen = gen;
            __threadfence();
            if (atomicAdd(&g_bar_cnt, 1u) == (unsigned)(NBK - 1)) {
                g_bar_cnt = 0;
                __threadfence();
                *(volatile unsigned*)&g_bar_gen = gen + 1;
                s_st = 1;
            } else s_st = 0;
        }
        __syncthreads();
        if (!s_st) {
            bool da = (pa < 0), db = (pb < 0);   // tid0-local pool-exhausted flags
            for (;;) {
                if (tid == 0) {
                    if (*(volatile unsigned*)&g_bar_gen != s_gen) { s_st = 1; }
                    else {
                        s_st = 0;
                        int p = -1, idx = 0, tt = 0;
                        if (!da) {
                            int v = atomicAdd(&g_tick[ta][pa], 1);
                            if (v < sza) { p = pa; idx = v; tt = ta; } else da = true;
                        }
                        if (p < 0 && !db) {
                            int v = atomicAdd(&g_tick[tb][pb], 1);
                            if (v < szb) { p = pb; idx = v; tt = tb; } else db = true;
                        }
                        s_pool = p; s_idx = idx; s_t = tt;
                    }
                }
                __syncthreads();
                if (s_st) break;
                int p = s_pool, idx = s_idx, tt = s_t;
                __syncthreads();
                if (p >= 0) gemm_bu(p, idx, tt, tid, Wih1, Whh1, Wih2, Whh2, s_as, s_ws);
            }
        }
        __threadfence();
        __syncthreads();
    };

    // ======== init: states + zero tickets ========
    for (int vb = blockIdx.x; vb < 64; vb += NBK) {
        int i = vb * NTHR + tid;
        int hh = i >> 5, b = i & 31;
        g_h1T[0][i] = h1[hh];
        g_c1T[i]    = c1[hh];
        g_h2T[0][i] = h2[hh];
        g_c2T[i]    = c2[hh];
        g_h2BH[b * HH + hh] = h2[hh];
    }
    for (int i = blockIdx.x * NTHR + tid; i < TT * 8; i += NBK * NTHR)
        ((int*)g_tick)[i] = 0;

    // ======== precompute sA2 ========
    for (int i = tid; i < CC; i += NTHR) s_wsc[i] = W_sC21[i];
    __syncthreads();
    for (int vb = blockIdx.x; vb < 320; vb += NBK) {
        int sub = tid >> 8;
        int p = tid & 255;
        int bt = vb * 2 + sub;
        int b = bt / TT, t = bt % TT;
        if (p < PP) {
            const float* vbp = videos + (((size_t)b * TT + t) * CC) * PP + p;
            float acc = 0.f;
#pragma unroll 8
            for (int c = 0; c < CC; c++) acc = fmaf(vbp[(size_t)c * PP], s_wsc[c], acc);
            g_sA2[(t * BB + b) * PP + p] = acc + b_sC21[0];
        }
    }
    barrier_slack(-1, 0, 0, -1, 0, 0);

    // ======== time loop ========
    for (int t = 0; t < TT; t++) {
        // ---- P1: attention logits + fc(prev) ----
        for (;;) {
            __syncthreads();
            if (tid == 0) s_u = atomicAdd(&g_tick[t][PL_ATTN], 1);
            __syncthreads();
            int u = s_u;
            if (u >= SZ_ATTN) break;
            int b = u >> 3, chunk = u & 7;
            if (tid < 256) ((float4*)s_h2)[tid] = ((const float4*)(g_h2BH + b * HH))[tid];
            __syncthreads();
            const float4* h2v = (const float4*)s_h2;
            if (chunk < 7) {
                for (int sub = w; sub < 28; sub += 16) {
                    int p = chunk * 28 + sub;
                    const float4* wr = (const float4*)(W_h2p + (size_t)p * HH);
                    float s = 0.f;
                    for (int i = lane; i < HH / 4; i += 32) {
                        float4 wv = wr[i]; float4 a = h2v[i];
                        s = fmaf(a.x, wv.x, s); s = fmaf(a.y, wv.y, s);
                        s = fmaf(a.z, wv.z, s); s = fmaf(a.w, wv.w, s);
                    }
                    for (int o = 16; o; o >>= 1) s += __shfl_down_sync(0xffffffffu, s, o);
                    if (lane == 0)
                        g_alogits[b * 208 + p] = s + b_h2p[p] + g_sA2[(t * BB + b) * PP + p] + spatialBias[p];
                }
            } else if (t > 0) {
                for (int nc = w; nc < NCC; nc += 16) {
                    const float4* wr = (const float4*)(W_fc + (size_t)nc * HH);
                    float s = 0.f;
                    for (int i = lane; i < HH / 4; i += 32) {
                        float4 wv = wr[i]; float4 a = h2v[i];
                        s = fmaf(a.x, wv.x, s); s = fmaf(a.y, wv.y, s);
                        s = fmaf(a.z, wv.z, s); s = fmaf(a.w, wv.w, s);
                    }
                    for (int o = 16; o; o >>= 1) s += __shfl_down_sync(0xffffffffu, s, o);
                    if (lane == 0) g_outs[((t - 1) * BB + b) * NCC + nc] = s + b_fc[nc];
                }
            }
            __syncthreads();
        }
        barrier_slack(PL_G1R, SZ_G1R, t, PL_G2R, SZ_G2R, t);

        // ---- P2: softmax + Y gather ----
        for (;;) {
            __syncthreads();
            if (tid == 0) s_u = atomicAdd(&g_tick[t][PL_SG], 1);
            __syncthreads();
            int u = s_u;
            if (u >= SZ_SG) break;
            int b = u >> 3, cs = u & 7;
            float v = -FLT_MAX;
            if (tid < 256) {
                v = (tid < PP) ? g_alogits[b * 208 + tid] : -FLT_MAX;
                s_red[tid] = v;
            }
            __syncthreads();
            for (int s = 128; s > 0; s >>= 1) { if (tid < s) s_red[tid] = fmaxf(s_red[tid], s_red[tid + s]); __syncthreads(); }
            float m = s_red[0]; __syncthreads();
            float e = (tid < PP) ? expf(v - m) : 0.f;
            if (tid < 256) s_red[tid] = e;
            __syncthreads();
            for (int s = 128; s > 0; s >>= 1) { if (tid < s) s_red[tid] += s_red[tid + s]; __syncthreads(); }
            float inv = 1.f / s_red[0];
            if (tid < PP) {
                float a = e * inv;
                s_al[tid] = a;
                if (cs == 0) g_alphas[(t * BB + b) * PP + tid] = a;
            }
            __syncthreads();
            const float4* al4 = (const float4*)s_al;
            const float* vbp = videos + ((size_t)(b * TT + t) * CC) * PP;
            int c = cs * 64 + w * 4;
            const float4* vr0 = (const float4*)(vbp + (size_t)(c + 0) * PP);
            const float4* vr1 = (const float4*)(vbp + (size_t)(c + 1) * PP);
            const float4* vr2 = (const float4*)(vbp + (size_t)(c + 2) * PP);
            const float4* vr3 = (const float4*)(vbp + (size_t)(c + 3) * PP);
            float s0 = 0.f, s1 = 0.f, s2 = 0.f, s3 = 0.f;
            for (int i = lane; i < 49; i += 32) {
                float4 a = al4[i];
                float4 v0 = vr0[i], v1 = vr1[i], v2 = vr2[i], v3 = vr3[i];
                s0 = fmaf(a.x, v0.x, s0); s0 = fmaf(a.y, v0.y, s0); s0 = fmaf(a.z, v0.z, s0); s0 = fmaf(a.w, v0.w, s0);
                s1 = fmaf(a.x, v1.x, s1); s1 = fmaf(a.y, v1.y, s1); s1 = fmaf(a.z, v1.z, s1); s1 = fmaf(a.w, v1.w, s1);
                s2 = fmaf(a.x, v2.x, s2); s2 = fmaf(a.y, v2.y, s2); s2 = fmaf(a.z, v2.z, s2); s2 = fmaf(a.w, v2.w, s2);
                s3 = fmaf(a.x, v3.x, s3); s3 = fmaf(a.y, v3.y, s3); s3 = fmaf(a.z, v3.z, s3); s3 = fmaf(a.w, v3.w, s3);
            }
            for (int o = 16; o; o >>= 1) {
                s0 += __shfl_down_sync(0xffffffffu, s0, o);
                s1 += __shfl_down_sync(0xffffffffu, s1, o);
                s2 += __shfl_down_sync(0xffffffffu, s2, o);
                s3 += __shfl_down_sync(0xffffffffu, s3, o);
            }
            if (lane == 0) {
                g_YT[(c + 0) * BB + b] = s0;
                g_YT[(c + 1) * BB + b] = s1;
                g_YT[(c + 2) * BB + b] = s2;
                g_YT[(c + 3) * BB + b] = s3;
            }
            __syncthreads();
        }
        barrier_slack(PL_G1R, SZ_G1R, t, PL_G2R, SZ_G2R, t);

        // ---- P3: gemm1 input half + finish recurrent half ----
        for (;;) {
            __syncthreads();
            if (tid == 0) s_u = atomicAdd(&g_tick[t][PL_G1I], 1);
            __syncthreads();
            int u = s_u;
            if (u >= SZ_G1I) break;
            gemm_bu(PL_G1I, u, t, tid, Wih1, Whh1, Wih2, Whh2, s_as, s_ws);
        }
        for (;;) {
            __syncthreads();
            if (tid == 0) s_u = atomicAdd(&g_tick[t][PL_G1R], 1);
            __syncthreads();
            int u = s_u;
            if (u >= SZ_G1R) break;
            gemm_bu(PL_G1R, u, t, tid, Wih1, Whh1, Wih2, Whh2, s_as, s_ws);
        }
        barrier_slack(PL_G2R, SZ_G2R, t, -1, 0, 0);

        // ---- P4: epilogue cell 1 (+ beta as unit 64) ----
        for (;;) {
            __syncthreads();
            if (tid == 0) s_u = atomicAdd(&g_tick[t][PL_EPI1], 1);
            __syncthreads();
            int u = s_u;
            if (u >= SZ_EPI1) break;
            if (u < 64) {
                int i = u * NTHR + tid;
                int jj = i >> 5, b = i & 31;
                float gv[4];
#pragma unroll
                for (int g = 0; g < 4; g++) {
                    float s = bih1[g * HH + jj] + bhh1[g * HH + jj];
#pragma unroll
                    for (int sg = 0; sg < NSEG1; sg++)
                        s += g_part1[sg][(jj * 4 + g) * BB + b];
                    gv[g] = s;
                }
                int idx = jj * BB + b;
                float cn = sigm(gv[1]) * g_c1T[idx] + sigm(gv[0]) * tanhf(gv[2]);
                g_c1T[idx] = cn;
                g_h1T[(t + 1) & 1][idx] = sigm(gv[3]) * tanhf(cn);
            } else {
#pragma unroll
                for (int rr = 0; rr < 2; rr++) {
                    int b = w * 2 + rr;
                    const float* h2r = g_h2BH + b * HH;
                    float s = 0.f;
                    for (int hh = lane; hh < HH; hh += 32) s = fmaf(h2r[hh], W_h21[hh], s);
                    for (int cc = lane; cc < CC; cc += 32) s = fmaf(g_YT[cc * BB + b], W_tC21[cc], s);
                    for (int o = 16; o; o >>= 1) s += __shfl_down_sync(0xffffffffu, s, o);
                    if (lane == 0)
                        g_betas[t * BB + b] = s + b_h21[0] + b_tC21[0] + temporalBias[0];
                }
            }
            __syncthreads();
        }
        barrier_slack(PL_G2R, SZ_G2R, t, -1, 0, 0);

        // ---- P5: gemm2 input half + finish recurrent half ----
        for (;;) {
            __syncthreads();
            if (tid == 0) s_u = atomicAdd(&g_tick[t][PL_G2I], 1);
            __syncthreads();
            int u = s_u;
            if (u >= SZ_G2I) break;
            gemm_bu(PL_G2I, u, t, tid, Wih1, Whh1, Wih2, Whh2, s_as, s_ws);
        }
        for (;;) {
            __syncthreads();
            if (tid == 0) s_u = atomicAdd(&g_tick[t][PL_G2R], 1);
            __syncthreads();
            int u = s_u;
            if (u >= SZ_G2R) break;
            gemm_bu(PL_G2R, u, t, tid, Wih1, Whh1, Wih2, Whh2, s_as, s_ws);
        }
        if (t + 1 < TT) barrier_slack(PL_G1R, SZ_G1R, t + 1, -1, 0, 0);
        else            barrier_slack(-1, 0, 0, -1, 0, 0);

        // ---- P6: epilogue cell 2 ----
        for (;;) {
            __syncthreads();
            if (tid == 0) s_u = atomicAdd(&g_tick[t][PL_EPI2], 1);
            __syncthreads();
            int u = s_u;
            if (u >= SZ_EPI2) break;
            int i = u * NTHR + tid;
            int jj = i >> 5, b = i & 31;
            float gv[4];
#pragma unroll
            for (int g = 0; g < 4; g++) {
                float s = bih2[g * HH + jj] + bhh2[g * HH + jj];
#pragma unroll
                for (int sg = 0; sg < NSEG2; sg++)
                    s += g_part2[sg][(jj * 4 + g) * BB + b];
                gv[g] = s;
            }
            int idx = jj * BB + b;
            float cn = sigm(gv[1]) * g_c2T[idx] + sigm(gv[0]) * tanhf(gv[2]);
            float hn = sigm(gv[3]) * tanhf(cn);
            g_c2T[idx] = cn;
            g_h2T[(t + 1) & 1][idx] = hn;
            g_h2BH[b * HH + jj] = hn;
            __syncthreads();
        }
        if (t + 1 < TT) barrier_slack(PL_G1R, SZ_G1R, t + 1, -1, 0, 0);
        else            barrier_slack(-1, 0, 0, -1, 0, 0);
    }

    // ======== final: fc(t=19), temporal softmax, logits, alpha copy ========
    {
        const int NCOPY4 = (TT * BB * PP) / 4;
        const int NVB_FIN = 32 + (NCOPY4 + NTHR - 1) / NTHR;
        for (int vb = blockIdx.x; vb < NVB_FIN; vb += NBK) {
            if (vb < 32) {
                int b = vb;
                for (int i = tid; i < HH; i += NTHR) s_h2[i] = g_h2BH[b * HH + i];
                __syncthreads();
                for (int nc = w; nc < NCC; nc += 16) {
                    const float* wr = W_fc + (size_t)nc * HH;
                    float s = 0.f;
                    for (int hh = lane; hh < HH; hh += 32) s = fmaf(s_h2[hh], wr[hh], s);
                    for (int o = 16; o; o >>= 1) s += __shfl_down_sync(0xffffffffu, s, o);
                    if (lane == 0) g_outs[((TT - 1) * BB + b) * NCC + nc] = s + b_fc[nc];
                }
                __syncthreads();
                if (tid == 0) {
                    float m = -FLT_MAX;
                    for (int tt = 0; tt < TT; tt++) m = fmaxf(m, g_betas[tt * BB + b]);
                    float s = 0.f;
                    for (int tt = 0; tt < TT; tt++) { float e = expf(g_betas[tt * BB + b] - m); s_bw[tt] = e; s += e; }
                    float inv = 1.f / s;
                    for (int tt = 0; tt < TT; tt++) {
                        s_bw[tt] *= inv;
                        if (write_betas) out[LOGITS + ALPHAS + b * TT + tt] = s_bw[tt];
                    }
                }
                __syncthreads();
                for (int nc = tid; nc < NCC; nc += NTHR) {
                    float s = 0.f;
                    for (int tt = 0; tt < TT; tt++) s = fmaf(s_bw[tt], g_outs[(tt * BB + b) * NCC + nc], s);
                    out[b * NCC + nc] = s;
                }
                __syncthreads();
            } else if (write_alphas) {
                int i = (vb - 32) * NTHR + tid;
                if (i < NCOPY4)
                    ((float4*)(out + LOGITS))[i] = ((const float4*)g_alphas)[i];
            }
        }
    }
}

// ---------------- launch ----------------
extern "C" void kernel_launch(void* const* d_in, const int* in_sizes, int n_in,
                              void* d_out, int out_size) {
    const float* videos       = (const float*)d_in[0];
    const float* h1           = (const float*)d_in[1];
    const float* c1           = (const float*)d_in[2];
    const float* h2           = (const float*)d_in[3];
    const float* c2           = (const float*)d_in[4];
    const float* spatialBias  = (const float*)d_in[5];
    const float* temporalBias = (const float*)d_in[6];
    const float* W_h2p        = (const float*)d_in[7];
    const float* b_h2p        = (const float*)d_in[8];
    const float* W_sC21       = (const float*)d_in[9];
    const float* b_sC21       = (const float*)d_in[10];
    const float* W_h21        = (const float*)d_in[11];
    const float* b_h21        = (const float*)d_in[12];
    const float* W_tC21       = (const float*)d_in[13];
    const float* b_tC21       = (const float*)d_in[14];
    const float* Wih1         = (const float*)d_in[15];
    const float* Whh1         = (const float*)d_in[16];
    const float* bih1         = (const float*)d_in[17];
    const float* bhh1         = (const float*)d_in[18];
    const float* Wih2         = (const float*)d_in[19];
    const float* Whh2         = (const float*)d_in[20];
    const float* bih2         = (const float*)d_in[21];
    const float* bhh2         = (const float*)d_in[22];
    const float* W_fc         = (const float*)d_in[23];
    const float* b_fc         = (const float*)d_in[24];

    float* out = (float*)d_out;
    const int LOGITS = BB * NCC;
    const int ALPHAS = TT * BB * PP;
    const int BETAS  = BB * TT;
    int write_alphas = (out_size >= LOGITS + ALPHAS);
    int write_betas  = (out_size >= LOGITS + ALPHAS + BETAS);

    mega_kernel<<<148, NTHR>>>(videos, h1, c1, h2, c2, spatialBias, temporalBias,
                               W_h2p, b_h2p, W_sC21, b_sC21, W_h21, b_h21,
                               W_tC21, b_tC21, Wih1, Whh1, bih1, bhh1,
                               Wih2, Whh2, bih2, bhh2, W_fc, b_fc,
                               out, write_alphas, write_betas);
}